// round 2
// baseline (speedup 1.0000x reference)
#include <cuda_runtime.h>

#define NN 100000
#define EE 1600000
#define FIN 128
#define HD 64
#define TILE 256
#define XS_STRIDE 257
#define HS_STRIDE 257

// Scratch (77 MB total) — __device__ globals, no allocation.
__device__ float g_k[(size_t)NN * HD];
__device__ float g_q[(size_t)NN * HD];
__device__ float g_vw[(size_t)NN * HD];

// hs column is private per thread (write own column, read own column) -> no syncs needed.
__device__ __forceinline__ void matvec64(const float* __restrict__ hs, int tid,
                                         const float* __restrict__ wt,
                                         const float* __restrict__ b,
                                         float* acc) {
    #pragma unroll
    for (int j = 0; j < HD; j++) acc[j] = b[j];
    #pragma unroll 2
    for (int l = 0; l < HD; l++) {
        float hl = hs[l * HS_STRIDE + tid];
        const float4* wr = (const float4*)(wt + l * 64);
        #pragma unroll
        for (int j4 = 0; j4 < 16; j4++) {
            float4 w = wr[j4];
            acc[4*j4+0] = fmaf(hl, w.x, acc[4*j4+0]);
            acc[4*j4+1] = fmaf(hl, w.y, acc[4*j4+1]);
            acc[4*j4+2] = fmaf(hl, w.z, acc[4*j4+2]);
            acc[4*j4+3] = fmaf(hl, w.w, acc[4*j4+3]);
        }
    }
}

__global__ __launch_bounds__(TILE)
void node_kernel(const float* __restrict__ x,
                 const float* __restrict__ W1, const float* __restrict__ b1,
                 const float* __restrict__ W2, const float* __restrict__ b2,
                 const float* __restrict__ Wk, const float* __restrict__ bk,
                 const float* __restrict__ Wq, const float* __restrict__ bq,
                 const float* __restrict__ Wv, const float* __restrict__ bv,
                 const float* __restrict__ Ws, const float* __restrict__ b_gate,
                 const float* __restrict__ Wsc, const float* __restrict__ bsc,
                 float* __restrict__ out)
{
    extern __shared__ float sm[];
    float* w1t = sm;                    // 8192  : W1 transposed [i=128][j=64]
    float* w2t = w1t + 8192;            // 4096  each, transposed [l][j]
    float* wkt = w2t + 4096;
    float* wqt = wkt + 4096;
    float* wvt = wqt + 4096;
    float* bb  = wvt + 4096;            // 512: b1|b2|bk|bq|bv|wsc|u|c0
    float* xs  = bb + 512;              // 32 * 257
    float* hs  = xs + 32 * XS_STRIDE;   // 64 * 257

    const int tid = threadIdx.x;

    // Stage weights (transposed for broadcast-friendly inner loops)
    for (int idx = tid; idx < 8192; idx += TILE) {
        int j = idx >> 7, i = idx & 127;
        w1t[i * 64 + j] = W1[idx];
    }
    for (int idx = tid; idx < 4096; idx += TILE) {
        int j = idx >> 6, l = idx & 63;
        w2t[l * 64 + j] = W2[idx];
        wkt[l * 64 + j] = Wk[idx];
        wqt[l * 64 + j] = Wq[idx];
        wvt[l * 64 + j] = Wv[idx];
    }
    if (tid < 64) {
        bb[tid]       = b1[tid];
        bb[64  + tid] = b2[tid];
        bb[128 + tid] = bk[tid];
        bb[192 + tid] = bq[tid];
        bb[256 + tid] = bv[tid];
        bb[320 + tid] = Wsc[tid];
        // u[l] = sum_j Ws[j,l] * wsc[j]   (skip path folded into scalar score)
        float s = 0.f;
        for (int j = 0; j < 64; j++) s = fmaf(Ws[j * 64 + tid], Wsc[j], s);
        bb[384 + tid] = s;
    }
    if (tid == 0) {
        float s = bsc[0];
        for (int j = 0; j < 64; j++) s = fmaf(b_gate[j], Wsc[j], s);
        bb[448] = s;  // c0
    }
    __syncthreads();

    const int node = blockIdx.x * TILE + tid;
    const bool active = node < NN;

    // ---- Layer 1: h1 = relu(x @ W1^T + b1), K=128 chunked by 32 ----
    float acc[HD];
    #pragma unroll
    for (int j = 0; j < HD; j++) acc[j] = bb[j];

    for (int c = 0; c < 4; c++) {
        if (c) __syncthreads();
        // cooperative, coalesced float4 load of x chunk, stored transposed
        for (int idx = tid; idx < 2048; idx += TILE) {
            int n = idx >> 3, i4 = idx & 7;
            int nn = blockIdx.x * TILE + n;
            float4 v = (nn < NN) ? ((const float4*)x)[(size_t)nn * 32 + c * 8 + i4]
                                 : make_float4(0.f, 0.f, 0.f, 0.f);
            xs[(4*i4+0) * XS_STRIDE + n] = v.x;
            xs[(4*i4+1) * XS_STRIDE + n] = v.y;
            xs[(4*i4+2) * XS_STRIDE + n] = v.z;
            xs[(4*i4+3) * XS_STRIDE + n] = v.w;
        }
        __syncthreads();
        #pragma unroll 2
        for (int i = 0; i < 32; i++) {
            float xi = xs[i * XS_STRIDE + tid];
            const float4* wr = (const float4*)(w1t + (c * 32 + i) * 64);
            #pragma unroll
            for (int j4 = 0; j4 < 16; j4++) {
                float4 w = wr[j4];
                acc[4*j4+0] = fmaf(xi, w.x, acc[4*j4+0]);
                acc[4*j4+1] = fmaf(xi, w.y, acc[4*j4+1]);
                acc[4*j4+2] = fmaf(xi, w.z, acc[4*j4+2]);
                acc[4*j4+3] = fmaf(xi, w.w, acc[4*j4+3]);
            }
        }
    }
    #pragma unroll
    for (int j = 0; j < HD; j++) hs[j * HS_STRIDE + tid] = fmaxf(acc[j], 0.f);

    // ---- Layer 2: h2 = h1 @ W2^T + b2 ----
    float h2[HD];
    matvec64(hs, tid, w2t, bb + 64, h2);

    // base score: h2 . u + c0  (skip + biases folded)
    float sc = bb[448];
    #pragma unroll
    for (int j = 0; j < HD; j++) sc = fmaf(h2[j], bb[384 + j], sc);
    if (active) out[node] = sc;

    #pragma unroll
    for (int j = 0; j < HD; j++) hs[j * HS_STRIDE + tid] = h2[j];

    // ---- k / q / vw heads ----
    matvec64(hs, tid, wkt, bb + 128, acc);
    if (active) {
        float4* o = (float4*)(g_k + (size_t)node * 64);
        #pragma unroll
        for (int j4 = 0; j4 < 16; j4++)
            o[j4] = make_float4(acc[4*j4], acc[4*j4+1], acc[4*j4+2], acc[4*j4+3]);
    }
    matvec64(hs, tid, wqt, bb + 192, acc);
    if (active) {
        float4* o = (float4*)(g_q + (size_t)node * 64);
        #pragma unroll
        for (int j4 = 0; j4 < 16; j4++)
            o[j4] = make_float4(acc[4*j4], acc[4*j4+1], acc[4*j4+2], acc[4*j4+3]);
    }
    matvec64(hs, tid, wvt, bb + 256, acc);
    #pragma unroll
    for (int j = 0; j < HD; j++) acc[j] *= bb[320 + j];  // vw = v * wsc
    if (active) {
        float4* o = (float4*)(g_vw + (size_t)node * 64);
        #pragma unroll
        for (int j4 = 0; j4 < 16; j4++)
            o[j4] = make_float4(acc[4*j4], acc[4*j4+1], acc[4*j4+2], acc[4*j4+3]);
    }
}

// One warp per edge: lane l handles features {2l, 2l+1} as float2.
// Scalar edge contribution: sum_h sigmoid(k[dst,h]+q[src,h]) * vw[src,h]
// edge_index delivered as int32 by the harness (int64 inputs are downcast).
__global__ __launch_bounds__(256)
void edge_kernel(const int* __restrict__ ei, float* __restrict__ out)
{
    int e = (blockIdx.x * blockDim.x + threadIdx.x) >> 5;
    if (e >= EE) return;
    int lane = threadIdx.x & 31;

    int src = ei[e];
    int dst = ei[EE + e];
    if ((unsigned)src >= NN || (unsigned)dst >= NN) return;  // safety net

    float2 kk = ((const float2*)(g_k  + (size_t)dst * 64))[lane];
    float2 qq = ((const float2*)(g_q  + (size_t)src * 64))[lane];
    float2 vv = ((const float2*)(g_vw + (size_t)src * 64))[lane];

    float s = __fdividef(1.f, 1.f + __expf(-(kk.x + qq.x))) * vv.x
            + __fdividef(1.f, 1.f + __expf(-(kk.y + qq.y))) * vv.y;

    #pragma unroll
    for (int o = 16; o > 0; o >>= 1) s += __shfl_down_sync(0xffffffffu, s, o);

    if (lane == 0) atomicAdd(out + dst, s);
}

extern "C" void kernel_launch(void* const* d_in, const int* in_sizes, int n_in,
                              void* d_out, int out_size)
{
    const float* x      = (const float*)d_in[0];
    const int*   ei     = (const int*)d_in[1];
    const float* W1     = (const float*)d_in[2];
    const float* b1     = (const float*)d_in[3];
    const float* W2     = (const float*)d_in[4];
    const float* b2     = (const float*)d_in[5];
    const float* Wk     = (const float*)d_in[6];
    const float* bk     = (const float*)d_in[7];
    const float* Wq     = (const float*)d_in[8];
    const float* bq     = (const float*)d_in[9];
    const float* Wv     = (const float*)d_in[10];
    const float* bv     = (const float*)d_in[11];
    const float* Ws     = (const float*)d_in[12];
    const float* b_gate = (const float*)d_in[13];
    const float* Wsc    = (const float*)d_in[14];
    const float* bsc    = (const float*)d_in[15];
    float* out = (float*)d_out;

    size_t smem = (8192 + 4 * 4096 + 512 + 32 * XS_STRIDE + 64 * HS_STRIDE) * sizeof(float);
    cudaFuncSetAttribute(node_kernel, cudaFuncAttributeMaxDynamicSharedMemorySize, (int)smem);

    node_kernel<<<(NN + TILE - 1) / TILE, TILE, smem>>>(
        x, W1, b1, W2, b2, Wk, bk, Wq, bq, Wv, bv, Ws, b_gate, Wsc, bsc, out);

    int eblocks = (EE * 32 + 255) / 256;  // 200000 blocks, warp-per-edge
    edge_kernel<<<eblocks, 256>>>(ei, out);
}

// round 3
// speedup vs baseline: 1.7455x; 1.7455x over previous
#include <cuda_runtime.h>
#include <cuda_bf16.h>

#define NN 100000
#define EE 1600000
#define TILE 256

// ---- device scratch (zero-init, no allocation) ----
__device__ float g_h1t[(size_t)64 * NN];        // h1 transposed [feat][node], 25.6MB
__device__ float g_At[3 * 64 * 64];             // composed head weights, at[h][l][i]
__device__ float g_bh[3 * 64];                  // composed head biases
__device__ float g_u[64];                       // Ws^T wsc
__device__ float g_u1[64];                      // W2^T u
__device__ float g_c1;                          // scalar score offset
__device__ __nv_bfloat16 g_kh[(size_t)NN * 64]; // bf16 k/q/vw, 12.8MB each
__device__ __nv_bfloat16 g_qh[(size_t)NN * 64];
__device__ __nv_bfloat16 g_vh[(size_t)NN * 64];

// ---------------- prologue: compose weights ----------------
__global__ void prec0(const float* __restrict__ Ws, const float* __restrict__ Wsc)
{
    int l = threadIdx.x;                 // 64 threads
    float u = 0.f;
    for (int j = 0; j < 64; j++) u = fmaf(Wsc[j], Ws[j * 64 + l], u);
    g_u[l] = u;
}

__global__ void prec1(const float* __restrict__ W2, const float* __restrict__ b2,
                      const float* __restrict__ Wk, const float* __restrict__ bk,
                      const float* __restrict__ Wq, const float* __restrict__ bq,
                      const float* __restrict__ Wv, const float* __restrict__ bv,
                      const float* __restrict__ b_gate,
                      const float* __restrict__ Wsc, const float* __restrict__ bsc)
{
    int id = blockIdx.x * 256 + threadIdx.x;
    if (id < 12288) {
        int head = id >> 12, rem = id & 4095;
        int l = rem >> 6, i = rem & 63;
        const float* Wh = head == 0 ? Wk : head == 1 ? Wq : Wv;
        float s = 0.f;
        for (int j = 0; j < 64; j++) s = fmaf(Wh[i * 64 + j], W2[j * 64 + l], s);
        if (head == 2) s *= Wsc[i];                   // fold wsc into Av
        g_At[head * 4096 + l * 64 + i] = s;
    } else if (id < 12352) {
        int i = id - 12288;
        float sk = bk[i], sq = bq[i], sv = bv[i];
        for (int j = 0; j < 64; j++) {
            sk = fmaf(Wk[i * 64 + j], b2[j], sk);
            sq = fmaf(Wq[i * 64 + j], b2[j], sq);
            sv = fmaf(Wv[i * 64 + j], b2[j], sv);
        }
        g_bh[i] = sk; g_bh[64 + i] = sq; g_bh[128 + i] = sv * Wsc[i];
        float u1 = 0.f;
        for (int l = 0; l < 64; l++) u1 = fmaf(g_u[l], W2[l * 64 + i], u1);
        g_u1[i] = u1;
        if (i == 0) {
            float c = bsc[0];
            for (int j = 0; j < 64; j++) c = fmaf(Wsc[j], b_gate[j], c);
            for (int l = 0; l < 64; l++) c = fmaf(g_u[l], b2[l], c);
            g_c1 = c;
        }
    }
}

// ---------------- N1: h1 = relu(x @ W1^T + b1) ----------------
__global__ __launch_bounds__(TILE)
void n1_kernel(const float* __restrict__ x,
               const float* __restrict__ W1, const float* __restrict__ b1)
{
    extern __shared__ float sm[];
    float* w1t = sm;                 // 8192 : [i=128][j=64]
    float* bb  = w1t + 8192;         // 64
    float* xs  = bb + 64;            // 32 * 257

    const int tid = threadIdx.x;
    for (int idx = tid; idx < 8192; idx += TILE) {
        int j = idx >> 7, i = idx & 127;
        w1t[i * 64 + j] = W1[idx];
    }
    if (tid < 64) bb[tid] = b1[tid];
    __syncthreads();

    const int node = blockIdx.x * TILE + tid;
    float acc[64];
    #pragma unroll
    for (int j = 0; j < 64; j++) acc[j] = bb[j];

    for (int c = 0; c < 4; c++) {
        if (c) __syncthreads();
        for (int idx = tid; idx < 2048; idx += TILE) {
            int n = idx >> 3, i4 = idx & 7;
            int nn = blockIdx.x * TILE + n;
            float4 v = (nn < NN) ? ((const float4*)x)[(size_t)nn * 32 + c * 8 + i4]
                                 : make_float4(0.f, 0.f, 0.f, 0.f);
            xs[(i4 * 4 + 0) * 257 + n] = v.x;
            xs[(i4 * 4 + 1) * 257 + n] = v.y;
            xs[(i4 * 4 + 2) * 257 + n] = v.z;
            xs[(i4 * 4 + 3) * 257 + n] = v.w;
        }
        __syncthreads();
        #pragma unroll 2
        for (int i = 0; i < 32; i++) {
            float xi = xs[i * 257 + tid];
            const float4* wr = (const float4*)(w1t + (c * 32 + i) * 64);
            #pragma unroll
            for (int j4 = 0; j4 < 16; j4++) {
                float4 w = wr[j4];
                acc[4*j4+0] = fmaf(xi, w.x, acc[4*j4+0]);
                acc[4*j4+1] = fmaf(xi, w.y, acc[4*j4+1]);
                acc[4*j4+2] = fmaf(xi, w.z, acc[4*j4+2]);
                acc[4*j4+3] = fmaf(xi, w.w, acc[4*j4+3]);
            }
        }
    }
    if (node < NN) {
        #pragma unroll
        for (int f = 0; f < 64; f++)
            g_h1t[(size_t)f * NN + node] = fmaxf(acc[f], 0.f);  // coalesced per feat
    }
}

// ---------------- N2: score + k/q/vw heads from h1 ----------------
__device__ __forceinline__ unsigned pack_bf2(float a, float b) {
    __nv_bfloat162 h = __floats2bfloat162_rn(a, b);
    return *reinterpret_cast<unsigned*>(&h);
}

__global__ __launch_bounds__(TILE, 2)
void n2_kernel(float* __restrict__ out)
{
    extern __shared__ float sm[];
    float* at = sm;             // 12288
    float* bb = at + 12288;     // 256: bh(192) | u1(64)
    float* hs = bb + 256;       // 64 * 256 (stride 256, conflict-free both ways)

    const int tid = threadIdx.x;
    const int base = blockIdx.x * TILE;

    for (int idx = tid; idx < 3072; idx += TILE)
        ((float4*)at)[idx] = ((const float4*)g_At)[idx];
    if (tid < 192) bb[tid] = g_bh[tid];
    if (tid < 64)  bb[192 + tid] = g_u1[tid];

    // stage h1 tile: hs[f][n] = g_h1t[f*NN + base + n], float4 coalesced
    for (int idx = tid; idx < 4096; idx += TILE) {
        int f = idx >> 6, n4 = idx & 63;
        int n = n4 * 4;
        float4 v = (base + n + 3 < NN)
                 ? *(const float4*)(g_h1t + (size_t)f * NN + base + n)
                 : make_float4(0.f, 0.f, 0.f, 0.f);
        *(float4*)(hs + f * 256 + n) = v;
    }
    __syncthreads();

    const int node = base + tid;
    const bool active = node < NN;

    // base score
    float sc = g_c1;
    #pragma unroll 4
    for (int l = 0; l < 64; l++) sc = fmaf(hs[l * 256 + tid], bb[192 + l], sc);
    if (active) out[node] = sc;

    // three heads
    #pragma unroll 1
    for (int h = 0; h < 3; h++) {
        float acc[64];
        #pragma unroll
        for (int j = 0; j < 64; j++) acc[j] = bb[h * 64 + j];
        const float* ah = at + h * 4096;
        #pragma unroll 2
        for (int l = 0; l < 64; l++) {
            float hl = hs[l * 256 + tid];
            const float4* wr = (const float4*)(ah + l * 64);
            #pragma unroll
            for (int j4 = 0; j4 < 16; j4++) {
                float4 w = wr[j4];
                acc[4*j4+0] = fmaf(hl, w.x, acc[4*j4+0]);
                acc[4*j4+1] = fmaf(hl, w.y, acc[4*j4+1]);
                acc[4*j4+2] = fmaf(hl, w.z, acc[4*j4+2]);
                acc[4*j4+3] = fmaf(hl, w.w, acc[4*j4+3]);
            }
        }
        if (active) {
            __nv_bfloat16* dp = (h == 0) ? g_kh : (h == 1) ? g_qh : g_vh;
            uint4* o = (uint4*)(dp + (size_t)node * 64);
            #pragma unroll
            for (int g = 0; g < 8; g++) {
                uint4 u;
                u.x = pack_bf2(acc[8*g+0], acc[8*g+1]);
                u.y = pack_bf2(acc[8*g+2], acc[8*g+3]);
                u.z = pack_bf2(acc[8*g+4], acc[8*g+5]);
                u.w = pack_bf2(acc[8*g+6], acc[8*g+7]);
                o[g] = u;
            }
        }
    }
}

// ---------------- edge kernel: 8 lanes per edge, bf16 ----------------
__device__ __forceinline__ float sigf(float x) {
    float t;
    asm("tanh.approx.f32 %0, %1;" : "=f"(t) : "f"(x * 0.5f));
    return fmaf(t, 0.5f, 0.5f);
}
__device__ __forceinline__ float2 bf2f(unsigned u) {
    __nv_bfloat162 h = *reinterpret_cast<__nv_bfloat162*>(&u);
    return __bfloat1622float2(h);
}

__global__ __launch_bounds__(256)
void edge_kernel(const int* __restrict__ ei, float* __restrict__ out)
{
    int t = blockIdx.x * 256 + threadIdx.x;
    int e = t >> 3;
    if (e >= EE) return;
    int sub = t & 7;

    int src = ei[e];
    int dst = ei[EE + e];

    const uint4 kk = *(const uint4*)(g_kh + (size_t)dst * 64 + sub * 8);
    const uint4 qq = *(const uint4*)(g_qh + (size_t)src * 64 + sub * 8);
    const uint4 vv = *(const uint4*)(g_vh + (size_t)src * 64 + sub * 8);

    float s = 0.f;
    {
        float2 kf = bf2f(kk.x), qf = bf2f(qq.x), vf = bf2f(vv.x);
        s += sigf(kf.x + qf.x) * vf.x + sigf(kf.y + qf.y) * vf.y;
    }
    {
        float2 kf = bf2f(kk.y), qf = bf2f(qq.y), vf = bf2f(vv.y);
        s += sigf(kf.x + qf.x) * vf.x + sigf(kf.y + qf.y) * vf.y;
    }
    {
        float2 kf = bf2f(kk.z), qf = bf2f(qq.z), vf = bf2f(vv.z);
        s += sigf(kf.x + qf.x) * vf.x + sigf(kf.y + qf.y) * vf.y;
    }
    {
        float2 kf = bf2f(kk.w), qf = bf2f(qq.w), vf = bf2f(vv.w);
        s += sigf(kf.x + qf.x) * vf.x + sigf(kf.y + qf.y) * vf.y;
    }

    s += __shfl_down_sync(0xffffffffu, s, 4, 8);
    s += __shfl_down_sync(0xffffffffu, s, 2, 8);
    s += __shfl_down_sync(0xffffffffu, s, 1, 8);
    if (sub == 0) atomicAdd(out + dst, s);
}

extern "C" void kernel_launch(void* const* d_in, const int* in_sizes, int n_in,
                              void* d_out, int out_size)
{
    const float* x      = (const float*)d_in[0];
    const int*   ei     = (const int*)d_in[1];
    const float* W1     = (const float*)d_in[2];
    const float* b1     = (const float*)d_in[3];
    const float* W2     = (const float*)d_in[4];
    const float* b2     = (const float*)d_in[5];
    const float* Wk     = (const float*)d_in[6];
    const float* bk     = (const float*)d_in[7];
    const float* Wq     = (const float*)d_in[8];
    const float* bq     = (const float*)d_in[9];
    const float* Wv     = (const float*)d_in[10];
    const float* bv     = (const float*)d_in[11];
    const float* Ws     = (const float*)d_in[12];
    const float* b_gate = (const float*)d_in[13];
    const float* Wsc    = (const float*)d_in[14];
    const float* bsc    = (const float*)d_in[15];
    float* out = (float*)d_out;

    static int inited = 0;
    size_t smem1 = (8192 + 64 + 32 * 257) * sizeof(float);              // 65.9 KB
    size_t smem2 = (12288 + 256 + 64 * 256) * sizeof(float);            // 113.0 KB
    if (!inited) {
        cudaFuncSetAttribute(n1_kernel, cudaFuncAttributeMaxDynamicSharedMemorySize, (int)smem1);
        cudaFuncSetAttribute(n2_kernel, cudaFuncAttributeMaxDynamicSharedMemorySize, (int)smem2);
        inited = 1;
    }

    prec0<<<1, 64>>>(Ws, Wsc);
    prec1<<<49, 256>>>(W2, b2, Wk, bk, Wq, bq, Wv, bv, b_gate, Wsc, bsc);

    int nblocks = (NN + TILE - 1) / TILE;  // 391
    n1_kernel<<<nblocks, TILE, smem1>>>(x, W1, b1);
    n2_kernel<<<nblocks, TILE, smem2>>>(out);

    edge_kernel<<<(EE * 8) / 256, 256>>>(ei, out);  // 50000 blocks
}

// round 4
// speedup vs baseline: 1.8015x; 1.0321x over previous
#include <cuda_runtime.h>
#include <cuda_bf16.h>

#define NN 100000
#define EE 1600000
#define TILE 256

#define FMA_F32X2(d, a, b, c) \
    asm("fma.rn.f32x2 %0, %1, %2, %3;" : "=l"(d) : "l"(a), "l"(b), "l"(c))
#define PACK_DUP_F32X2(out, f) do { \
    unsigned _u = __float_as_uint(f); \
    asm("mov.b64 %0, {%1, %1};" : "=l"(out) : "r"(_u)); } while (0)
#define UNPACK_F32X2(lo, hi, in) \
    asm("mov.b64 {%0, %1}, %2;" : "=f"(lo), "=f"(hi) : "l"(in))

// ---- device scratch (no allocation) ----
__device__ float g_h1t[(size_t)64 * NN];        // h1 transposed [feat][node]
__device__ float g_At[3 * 64 * 64];             // composed head weights
__device__ float g_bh[3 * 64];                  // composed head biases
__device__ float g_u[64];                       // Ws^T wsc
__device__ float g_u1[64];                      // W2^T u
__device__ float g_c1;
__device__ __nv_bfloat16 g_kh[(size_t)NN * 64];
__device__ __nv_bfloat16 g_qh[(size_t)NN * 64];
__device__ __nv_bfloat16 g_vh[(size_t)NN * 64];

// ---------------- prologue ----------------
__global__ void prec0(const float* __restrict__ Ws, const float* __restrict__ Wsc)
{
    int l = threadIdx.x;
    float u = 0.f;
    for (int j = 0; j < 64; j++) u = fmaf(Wsc[j], Ws[j * 64 + l], u);
    g_u[l] = u;
}

__global__ void prec1(const float* __restrict__ W2, const float* __restrict__ b2,
                      const float* __restrict__ Wk, const float* __restrict__ bk,
                      const float* __restrict__ Wq, const float* __restrict__ bq,
                      const float* __restrict__ Wv, const float* __restrict__ bv,
                      const float* __restrict__ b_gate,
                      const float* __restrict__ Wsc, const float* __restrict__ bsc)
{
    int id = blockIdx.x * 256 + threadIdx.x;
    if (id < 12288) {
        int head = id >> 12, rem = id & 4095;
        int l = rem >> 6, i = rem & 63;
        const float* Wh = head == 0 ? Wk : head == 1 ? Wq : Wv;
        float s = 0.f;
        for (int j = 0; j < 64; j++) s = fmaf(Wh[i * 64 + j], W2[j * 64 + l], s);
        if (head == 2) s *= Wsc[i];
        g_At[head * 4096 + l * 64 + i] = s;
    } else if (id < 12352) {
        int i = id - 12288;
        float sk = bk[i], sq = bq[i], sv = bv[i];
        for (int j = 0; j < 64; j++) {
            sk = fmaf(Wk[i * 64 + j], b2[j], sk);
            sq = fmaf(Wq[i * 64 + j], b2[j], sq);
            sv = fmaf(Wv[i * 64 + j], b2[j], sv);
        }
        g_bh[i] = sk; g_bh[64 + i] = sq; g_bh[128 + i] = sv * Wsc[i];
        float u1 = 0.f;
        for (int l = 0; l < 64; l++) u1 = fmaf(g_u[l], W2[l * 64 + i], u1);
        g_u1[i] = u1;
        if (i == 0) {
            float c = bsc[0];
            for (int j = 0; j < 64; j++) c = fmaf(Wsc[j], b_gate[j], c);
            for (int l = 0; l < 64; l++) c = fmaf(g_u[l], b2[l], c);
            g_c1 = c;
        }
    }
}

// ---------------- N1: h1 = relu(x @ W1^T + b1), packed f32x2 ----------------
__global__ __launch_bounds__(TILE)
void n1_kernel(const float* __restrict__ x,
               const float* __restrict__ W1, const float* __restrict__ b1)
{
    extern __shared__ float sm[];
    float* w1t = sm;                 // 8192 : [i=128][j=64]
    float* bb  = w1t + 8192;         // 64
    float* xs  = bb + 64;            // 32 * 257

    const int tid = threadIdx.x;
    for (int idx = tid; idx < 8192; idx += TILE) {
        int j = idx >> 7, i = idx & 127;
        w1t[i * 64 + j] = W1[idx];
    }
    if (tid < 64) bb[tid] = b1[tid];
    __syncthreads();

    const int node = blockIdx.x * TILE + tid;

    unsigned long long acc2[32];
    {
        const unsigned long long* bp = (const unsigned long long*)bb;
        #pragma unroll
        for (int j = 0; j < 32; j++) acc2[j] = bp[j];
    }

    for (int c = 0; c < 4; c++) {
        if (c) __syncthreads();
        for (int idx = tid; idx < 2048; idx += TILE) {
            int n = idx >> 3, i4 = idx & 7;
            int nn = blockIdx.x * TILE + n;
            float4 v = (nn < NN) ? ((const float4*)x)[(size_t)nn * 32 + c * 8 + i4]
                                 : make_float4(0.f, 0.f, 0.f, 0.f);
            xs[(i4 * 4 + 0) * 257 + n] = v.x;
            xs[(i4 * 4 + 1) * 257 + n] = v.y;
            xs[(i4 * 4 + 2) * 257 + n] = v.z;
            xs[(i4 * 4 + 3) * 257 + n] = v.w;
        }
        __syncthreads();
        #pragma unroll 2
        for (int i = 0; i < 32; i++) {
            float xi = xs[i * 257 + tid];
            unsigned long long xx; PACK_DUP_F32X2(xx, xi);
            const ulonglong2* wr = (const ulonglong2*)(w1t + (c * 32 + i) * 64);
            #pragma unroll
            for (int j2 = 0; j2 < 16; j2++) {
                ulonglong2 w = wr[j2];
                FMA_F32X2(acc2[2*j2+0], xx, w.x, acc2[2*j2+0]);
                FMA_F32X2(acc2[2*j2+1], xx, w.y, acc2[2*j2+1]);
            }
        }
    }
    if (node < NN) {
        #pragma unroll
        for (int j = 0; j < 32; j++) {
            float lo, hi;
            UNPACK_F32X2(lo, hi, acc2[j]);
            g_h1t[(size_t)(2*j+0) * NN + node] = fmaxf(lo, 0.f);
            g_h1t[(size_t)(2*j+1) * NN + node] = fmaxf(hi, 0.f);
        }
    }
}

// ---------------- N2: score + k/q/vw heads, packed f32x2 ----------------
__device__ __forceinline__ unsigned pack_bf2(float a, float b) {
    __nv_bfloat162 h = __floats2bfloat162_rn(a, b);
    return *reinterpret_cast<unsigned*>(&h);
}

__global__ __launch_bounds__(TILE, 2)
void n2_kernel(float* __restrict__ out)
{
    extern __shared__ float sm[];
    float* at = sm;             // 12288
    float* bb = at + 12288;     // 256: bh(192) | u1(64)
    float* hs = bb + 256;       // 64 * 256

    const int tid = threadIdx.x;
    const int base = blockIdx.x * TILE;

    for (int idx = tid; idx < 3072; idx += TILE)
        ((float4*)at)[idx] = ((const float4*)g_At)[idx];
    if (tid < 192) bb[tid] = g_bh[tid];
    if (tid < 64)  bb[192 + tid] = g_u1[tid];

    for (int idx = tid; idx < 4096; idx += TILE) {
        int f = idx >> 6, n4 = idx & 63;
        int n = n4 * 4;
        float4 v = (base + n + 3 < NN)
                 ? *(const float4*)(g_h1t + (size_t)f * NN + base + n)
                 : make_float4(0.f, 0.f, 0.f, 0.f);
        *(float4*)(hs + f * 256 + n) = v;
    }
    __syncthreads();

    const int node = base + tid;
    const bool active = node < NN;

    // base score (scalar fp32; negligible share of the FMA budget)
    float sc = g_c1;
    #pragma unroll 4
    for (int l = 0; l < 64; l++) sc = fmaf(hs[l * 256 + tid], bb[192 + l], sc);
    if (active) out[node] = sc;

    #pragma unroll 1
    for (int h = 0; h < 3; h++) {
        unsigned long long acc2[32];
        {
            const unsigned long long* bp = (const unsigned long long*)(bb + h * 64);
            #pragma unroll
            for (int j = 0; j < 32; j++) acc2[j] = bp[j];
        }
        const float* ah = at + h * 4096;
        #pragma unroll 2
        for (int l = 0; l < 64; l++) {
            float hl = hs[l * 256 + tid];
            unsigned long long hh; PACK_DUP_F32X2(hh, hl);
            const ulonglong2* wr = (const ulonglong2*)(ah + l * 64);
            #pragma unroll
            for (int j2 = 0; j2 < 16; j2++) {
                ulonglong2 w = wr[j2];
                FMA_F32X2(acc2[2*j2+0], hh, w.x, acc2[2*j2+0]);
                FMA_F32X2(acc2[2*j2+1], hh, w.y, acc2[2*j2+1]);
            }
        }
        if (active) {
            __nv_bfloat16* dp = (h == 0) ? g_kh : (h == 1) ? g_qh : g_vh;
            uint4* o = (uint4*)(dp + (size_t)node * 64);
            #pragma unroll
            for (int g = 0; g < 8; g++) {
                float a0, a1, b0, b1, c0, c1, d0, d1;
                UNPACK_F32X2(a0, a1, acc2[4*g+0]);
                UNPACK_F32X2(b0, b1, acc2[4*g+1]);
                UNPACK_F32X2(c0, c1, acc2[4*g+2]);
                UNPACK_F32X2(d0, d1, acc2[4*g+3]);
                uint4 u;
                u.x = pack_bf2(a0, a1);
                u.y = pack_bf2(b0, b1);
                u.z = pack_bf2(c0, c1);
                u.w = pack_bf2(d0, d1);
                o[g] = u;
            }
        }
    }
}

// ---------------- edge kernel: 8 lanes/edge, bf16 ----------------
__device__ __forceinline__ float sigf(float x) {
    float t;
    asm("tanh.approx.f32 %0, %1;" : "=f"(t) : "f"(x * 0.5f));
    return fmaf(t, 0.5f, 0.5f);
}
__device__ __forceinline__ float2 bf2f(unsigned u) {
    __nv_bfloat162 h = *reinterpret_cast<__nv_bfloat162*>(&u);
    return __bfloat1622float2(h);
}

__global__ __launch_bounds__(256)
void edge_kernel(const int* __restrict__ ei, float* __restrict__ out)
{
    int t = blockIdx.x * 256 + threadIdx.x;
    int e = t >> 3;
    if (e >= EE) return;
    int sub = t & 7;

    int src = ei[e];
    int dst = ei[EE + e];

    const uint4 kk = *(const uint4*)(g_kh + (size_t)dst * 64 + sub * 8);
    const uint4 qq = *(const uint4*)(g_qh + (size_t)src * 64 + sub * 8);
    const uint4 vv = *(const uint4*)(g_vh + (size_t)src * 64 + sub * 8);

    float s = 0.f;
    {
        float2 kf = bf2f(kk.x), qf = bf2f(qq.x), vf = bf2f(vv.x);
        s += sigf(kf.x + qf.x) * vf.x + sigf(kf.y + qf.y) * vf.y;
    }
    {
        float2 kf = bf2f(kk.y), qf = bf2f(qq.y), vf = bf2f(vv.y);
        s += sigf(kf.x + qf.x) * vf.x + sigf(kf.y + qf.y) * vf.y;
    }
    {
        float2 kf = bf2f(kk.z), qf = bf2f(qq.z), vf = bf2f(vv.z);
        s += sigf(kf.x + qf.x) * vf.x + sigf(kf.y + qf.y) * vf.y;
    }
    {
        float2 kf = bf2f(kk.w), qf = bf2f(qq.w), vf = bf2f(vv.w);
        s += sigf(kf.x + qf.x) * vf.x + sigf(kf.y + qf.y) * vf.y;
    }

    s += __shfl_down_sync(0xffffffffu, s, 4, 8);
    s += __shfl_down_sync(0xffffffffu, s, 2, 8);
    s += __shfl_down_sync(0xffffffffu, s, 1, 8);
    if (sub == 0) atomicAdd(out + dst, s);
}

extern "C" void kernel_launch(void* const* d_in, const int* in_sizes, int n_in,
                              void* d_out, int out_size)
{
    const float* x      = (const float*)d_in[0];
    const int*   ei     = (const int*)d_in[1];
    const float* W1     = (const float*)d_in[2];
    const float* b1     = (const float*)d_in[3];
    const float* W2     = (const float*)d_in[4];
    const float* b2     = (const float*)d_in[5];
    const float* Wk     = (const float*)d_in[6];
    const float* bk     = (const float*)d_in[7];
    const float* Wq     = (const float*)d_in[8];
    const float* bq     = (const float*)d_in[9];
    const float* Wv     = (const float*)d_in[10];
    const float* bv     = (const float*)d_in[11];
    const float* Ws     = (const float*)d_in[12];
    const float* b_gate = (const float*)d_in[13];
    const float* Wsc    = (const float*)d_in[14];
    const float* bsc    = (const float*)d_in[15];
    float* out = (float*)d_out;

    static int inited = 0;
    size_t smem1 = (8192 + 64 + 32 * 257) * sizeof(float);
    size_t smem2 = (12288 + 256 + 64 * 256) * sizeof(float);
    if (!inited) {
        cudaFuncSetAttribute(n1_kernel, cudaFuncAttributeMaxDynamicSharedMemorySize, (int)smem1);
        cudaFuncSetAttribute(n2_kernel, cudaFuncAttributeMaxDynamicSharedMemorySize, (int)smem2);
        inited = 1;
    }

    prec0<<<1, 64>>>(Ws, Wsc);
    prec1<<<49, 256>>>(W2, b2, Wk, bk, Wq, bq, Wv, bv, b_gate, Wsc, bsc);

    int nblocks = (NN + TILE - 1) / TILE;
    n1_kernel<<<nblocks, TILE, smem1>>>(x, W1, b1);
    n2_kernel<<<nblocks, TILE, smem2>>>(out);

    edge_kernel<<<(EE * 8) / 256, 256>>>(ei, out);
}